// round 14
// baseline (speedup 1.0000x reference)
#include <cuda_runtime.h>
#include <cuda_bf16.h>
#include <cstdint>

#define HW 16384
#define IMG 128

// ---------------- scratch (static __device__, no allocs) ----------------
__device__ float g_t[8L * 384 * HW];            // pos-conv output (B,384,H,W) fp32
__device__ float g_q[8L * 128 * HW];            // q channels fp32
__device__ float g_k[8L * 128 * HW];            // k channels fp32
__device__ __nv_bfloat16 g_yh[8L * 256 * HW];   // [v|d3|d5] split hi
__device__ __nv_bfloat16 g_yl[8L * 256 * HW];   // [v|d3|d5] split lo
__device__ __nv_bfloat16 g_wh[384 * 128];       // pos_w split hi
__device__ __nv_bfloat16 g_wl[384 * 128];       // pos_w split lo
__device__ __nv_bfloat16 g_Ah[8 * 128 * 256];   // folded proj*attn split hi
__device__ __nv_bfloat16 g_Al[8 * 128 * 256];   // folded proj*attn split lo
__device__ float g_gram[64 * 288];              // per (b,h): G[256], qn[16], kn[16]

__device__ __forceinline__ void split2(float v, __nv_bfloat16& h, __nv_bfloat16& l) {
    h = __float2bfloat16(v);
    l = __float2bfloat16(v - __bfloat162float(h));
}
__device__ __forceinline__ uint32_t smem_u32(const void* p) {
    uint32_t a;
    asm("{ .reg .u64 t; cvta.to.shared.u64 t, %1; cvt.u32.u64 %0, t; }" : "=r"(a) : "l"(p));
    return a;
}
__device__ __forceinline__ uint32_t pack_bf2(__nv_bfloat16 a, __nv_bfloat16 b) {
    return (uint32_t)__bfloat16_as_ushort(a) | ((uint32_t)__bfloat16_as_ushort(b) << 16);
}

// ---------------- zero gram accumulators ----------------
__global__ void zero_gram_k() {
    int i = blockIdx.x * 256 + threadIdx.x;
    if (i < 64 * 288) g_gram[i] = 0.f;
}

// ---------------- split conversion for pos_w ----------------
__global__ void convert_w_k(const float* __restrict__ w) {
    long i = ((long)blockIdx.x * 256 + threadIdx.x) * 4;
    float4 v = *(const float4*)(w + i);
    __nv_bfloat16 h, l;
    split2(v.x, h, l); g_wh[i + 0] = h; g_wl[i + 0] = l;
    split2(v.y, h, l); g_wh[i + 1] = h; g_wl[i + 1] = l;
    split2(v.z, h, l); g_wh[i + 2] = h; g_wl[i + 2] = l;
    split2(v.w, h, l); g_wh[i + 3] = h; g_wl[i + 3] = l;
}

// ---------------- mma.sync helpers ----------------
__device__ __forceinline__ void hmma(float* c, const uint32_t* a, uint32_t b0, uint32_t b1) {
    asm volatile(
        "mma.sync.aligned.m16n8k16.row.col.f32.bf16.bf16.f32 "
        "{%0,%1,%2,%3}, {%4,%5,%6,%7}, {%8,%9}, {%0,%1,%2,%3};"
        : "+f"(c[0]), "+f"(c[1]), "+f"(c[2]), "+f"(c[3])
        : "r"(a[0]), "r"(a[1]), "r"(a[2]), "r"(a[3]), "r"(b0), "r"(b1));
}
__device__ __forceinline__ void ldsm4(uint32_t* r, uint32_t addr) {
    asm volatile("ldmatrix.sync.aligned.m8n8.x4.shared.b16 {%0,%1,%2,%3}, [%4];"
        : "=r"(r[0]), "=r"(r[1]), "=r"(r[2]), "=r"(r[3]) : "r"(addr));
}
__device__ __forceinline__ void ldsm4t(uint32_t* r, uint32_t addr) {
    asm volatile("ldmatrix.sync.aligned.m8n8.x4.trans.shared.b16 {%0,%1,%2,%3}, [%4];"
        : "=r"(r[0]), "=r"(r[1]), "=r"(r[2]), "=r"(r[3]) : "r"(addr));
}

// ---------------- bf16-split GEMM, register double-buffered ----------------
#define A_STRIDE 40
#define B_STRIDE 136

template <int K, bool BSPLIT>
__device__ __forceinline__ void mmasync_body(
    const __nv_bfloat16* __restrict__ Ah, const __nv_bfloat16* __restrict__ Al,
    long aStride,
    const __nv_bfloat16* __restrict__ Bh, const __nv_bfloat16* __restrict__ Bl,
    const float* __restrict__ Bf, long bStride,
    float* __restrict__ C, long cStride, const float* __restrict__ bias)
{
    __shared__ __nv_bfloat16 sAH[64 * A_STRIDE];
    __shared__ __nv_bfloat16 sAL[64 * A_STRIDE];
    __shared__ __nv_bfloat16 sBH[32 * B_STRIDE];
    __shared__ __nv_bfloat16 sBL[32 * B_STRIDE];
    const uint32_t uAH = smem_u32(sAH), uAL = smem_u32(sAL);
    const uint32_t uBH = smem_u32(sBH), uBL = smem_u32(sBL);

    const int b = blockIdx.z;
    const int m0 = blockIdx.y * 64;
    const int n0 = blockIdx.x * 128;
    const int tid = threadIdx.x;
    const int wid = tid >> 5, lane = tid & 31;
    const int wm = (wid & 1) * 32, wn = (wid >> 1) * 64;
    const int g = lane >> 2, tq = lane & 3;
    const int lrow = lane & 15;
    const int lcol = (lane >> 4) * 8;

    const __nv_bfloat16* AhB = Ah + (long)b * aStride;
    const __nv_bfloat16* AlB = Al + (long)b * aStride;
    const __nv_bfloat16* BhB = BSPLIT ? Bh + (long)b * bStride : nullptr;
    const __nv_bfloat16* BlB = BSPLIT ? Bl + (long)b * bStride : nullptr;
    const float* BfB = BSPLIT ? nullptr : Bf + (long)b * bStride;

    const int ar = tid >> 2, ac = (tid & 3) * 8;
    const int br4 = tid >> 4, bc4 = (tid & 15) * 8;
    const int brf = tid >> 5, bcf = (tid & 31) * 4;

    uint4 rA[2][2];
    uint4 rB[4][2];
    float4 rBF[8];

    auto ldg_chunk = [&](int ch) {
        const int ko = ch * 32;
#pragma unroll
        for (int p = 0; p < 2; p++) {
            long go = (long)(m0 + ar + p * 32) * K + ko + ac;
            rA[p][0] = *(const uint4*)(AhB + go);
            rA[p][1] = *(const uint4*)(AlB + go);
        }
        if (BSPLIT) {
#pragma unroll
            for (int p = 0; p < 4; p++) {
                long go = (long)(ko + br4 + p * 8) * HW + n0 + bc4;
                rB[p][0] = *(const uint4*)(BhB + go);
                rB[p][1] = *(const uint4*)(BlB + go);
            }
        } else {
#pragma unroll
            for (int p = 0; p < 8; p++) {
                long go = (long)(ko + brf + p * 4) * HW + n0 + bcf;
                rBF[p] = *(const float4*)(BfB + go);
            }
        }
    };

    auto sts_chunk = [&]() {
#pragma unroll
        for (int p = 0; p < 2; p++) {
            int row = ar + p * 32;
            *(uint4*)(sAH + row * A_STRIDE + ac) = rA[p][0];
            *(uint4*)(sAL + row * A_STRIDE + ac) = rA[p][1];
        }
        if (BSPLIT) {
#pragma unroll
            for (int p = 0; p < 4; p++) {
                int row = br4 + p * 8;
                *(uint4*)(sBH + row * B_STRIDE + bc4) = rB[p][0];
                *(uint4*)(sBL + row * B_STRIDE + bc4) = rB[p][1];
            }
        } else {
#pragma unroll
            for (int p = 0; p < 8; p++) {
                int row = brf + p * 4;
                float4 v = rBF[p];
                __nv_bfloat16 h0, l0, h1, l1, h2, l2, h3, l3;
                split2(v.x, h0, l0); split2(v.y, h1, l1);
                split2(v.z, h2, l2); split2(v.w, h3, l3);
                uint2 hp = make_uint2(pack_bf2(h0, h1), pack_bf2(h2, h3));
                uint2 lp = make_uint2(pack_bf2(l0, l1), pack_bf2(l2, l3));
                *(uint2*)(sBH + row * B_STRIDE + bcf) = hp;
                *(uint2*)(sBL + row * B_STRIDE + bcf) = lp;
            }
        }
    };

    float c[2][8][4];
#pragma unroll
    for (int mi = 0; mi < 2; mi++)
#pragma unroll
        for (int nb = 0; nb < 8; nb++)
#pragma unroll
            for (int j = 0; j < 4; j++) c[mi][nb][j] = 0.f;

    const int NC = K / 32;
    ldg_chunk(0);
    for (int ch = 0; ch < NC; ch++) {
        sts_chunk();
        __syncthreads();
        if (ch + 1 < NC) ldg_chunk(ch + 1);

#pragma unroll
        for (int kc = 0; kc < 2; kc++) {
            uint32_t aH[2][4], aL[2][4];
#pragma unroll
            for (int mi = 0; mi < 2; mi++) {
                uint32_t off = (uint32_t)(((wm + mi * 16 + lrow) * A_STRIDE + kc * 16 + lcol) * 2);
                ldsm4(aH[mi], uAH + off);
                ldsm4(aL[mi], uAL + off);
            }
#pragma unroll
            for (int nbp = 0; nbp < 4; nbp++) {
                uint32_t off = (uint32_t)(((kc * 16 + lrow) * B_STRIDE + wn + nbp * 16 + lcol) * 2);
                uint32_t bH[4], bL[4];
                ldsm4t(bH, uBH + off);
                ldsm4t(bL, uBL + off);
                int nb = nbp * 2;
#pragma unroll
                for (int t = 0; t < 3; t++) {
                    const uint32_t (*af)[4] = (t == 1) ? aL : aH;
                    const uint32_t* bf = (t == 2) ? bL : bH;
#pragma unroll
                    for (int mi = 0; mi < 2; mi++) {
                        hmma(c[mi][nb],     af[mi], bf[0], bf[1]);
                        hmma(c[mi][nb + 1], af[mi], bf[2], bf[3]);
                    }
                }
            }
        }
        __syncthreads();
    }

#pragma unroll
    for (int mi = 0; mi < 2; mi++) {
        int r0 = m0 + wm + mi * 16 + g;
        float bv0 = bias ? bias[r0] : 0.f;
        float bv1 = bias ? bias[r0 + 8] : 0.f;
#pragma unroll
        for (int nb = 0; nb < 8; nb++) {
            int col = n0 + wn + nb * 8 + tq * 2;
            float* p0 = C + (long)b * cStride + (long)r0 * HW + col;
            float* p1 = p0 + 8L * HW;
            *(float2*)p0 = make_float2(c[mi][nb][0] + bv0, c[mi][nb][1] + bv0);
            *(float2*)p1 = make_float2(c[mi][nb][2] + bv1, c[mi][nb][3] + bv1);
        }
    }
}

__global__ __launch_bounds__(128) void k1_gemm(const float* __restrict__ x,
                                               const float* __restrict__ pb) {
    mmasync_body<128, false>(g_wh, g_wl, 0L, nullptr, nullptr, x, 128L * HW,
                             g_t, 384L * HW, pb);
}
__global__ __launch_bounds__(128) void k4_gemm(float* __restrict__ out) {
    mmasync_body<256, true>(g_Ah, g_Al, 128L * 256, g_yh, g_yl, nullptr, 256L * HW,
                            out, 128L * HW, nullptr);
}

// ---------------- dual grouped conv (3x3 + 5x5 sharing input pair) ----------------
// 32x64 output per CTA, 128 threads, 6 CTAs/SM.
// Halo layout SHIFTED: smem col j <-> gx = ox0 - 2 + j (j in [0,68), row pad 72).
// Window reads are float4-aligned (col px0): 2x LDS.128 per row instead of 8x LDS.32.
// Global float4 chunks (gx0 = ox0-4+4m, aligned) land at odd half-offsets -> float2 STS.
#define CONV_ROW 72
#define CONV_CH (36 * CONV_ROW)

template <int MODE>
__global__ __launch_bounds__(128, 6) void dualconv_k(
    const float* __restrict__ in_ext,
    const float* __restrict__ w3, const float* __restrict__ b3,
    const float* __restrict__ w5, const float* __restrict__ b5)
{
    const int Cin = (MODE == 0) ? 384 : 128;
    const float* in = (MODE == 0) ? (const float*)g_t : in_ext;

    __shared__ float s[2 * CONV_CH];
    __shared__ float sw[68];

    const int tile = blockIdx.x;                 // 0..7: 4 row-tiles x 2 col-tiles
    const int oy0 = (tile >> 1) * 32;
    const int ox0 = (tile & 1) * 64;
    const int g = blockIdx.y;
    const long bz = blockIdx.z;
    const int tid = threadIdx.x;
    const int ttx = tid & 15, tty = tid >> 4;    // 16x8 threads, 4x4 px each
    const int py0 = tty * 4, px0 = ttx * 4;

    const float* in0 = in + (bz * Cin + 2 * g) * (long)HW;

    // ---- halo load: rows 0..35 (gy = oy0-2+row); chunks m=0..17, gx0 = ox0-4+4m,
    //      stored at smem col j0 = 4m-2 (float2 stores, edges store half chunk).
    {
        const int lr = tid >> 4;     // 0..7: row within pass
        const int lc = tid & 15;     // chunk index (plus 16/17 for lc<2)
#pragma unroll
        for (int ch = 0; ch < 2; ch++) {
            const float* inc = in0 + ch * HW;
            float* sch = s + ch * CONV_CH;
#pragma unroll
            for (int rp = 0; rp < 40; rp += 8) {
                int r = rp + lr;
                if (r < 36) {
                    int gy = oy0 - 2 + r;
                    bool rowok = (unsigned)gy < 128u;
                    const float* rowp = inc + gy * IMG;
                    float* srow = sch + r * CONV_ROW;
                    // chunk m = lc (0..15)
                    {
                        int m = lc;
                        int gx0 = ox0 - 4 + m * 4;
                        float4 v = make_float4(0.f, 0.f, 0.f, 0.f);
                        if (rowok && (unsigned)gx0 < 125u) v = *(const float4*)(rowp + gx0);
                        if (m == 0) {
                            *(float2*)(srow + 0) = make_float2(v.z, v.w);
                        } else {
                            int j0 = m * 4 - 2;
                            *(float2*)(srow + j0) = make_float2(v.x, v.y);
                            *(float2*)(srow + j0 + 2) = make_float2(v.z, v.w);
                        }
                    }
                    // chunks m = 16, 17 handled by lc < 2
                    if (lc < 2) {
                        int m = 16 + lc;
                        int gx0 = ox0 - 4 + m * 4;
                        float4 v = make_float4(0.f, 0.f, 0.f, 0.f);
                        if (rowok && (unsigned)gx0 < 125u) v = *(const float4*)(rowp + gx0);
                        int j0 = m * 4 - 2;
                        if (m == 17) {
                            *(float2*)(srow + j0) = make_float2(v.x, v.y);
                        } else {
                            *(float2*)(srow + j0) = make_float2(v.x, v.y);
                            *(float2*)(srow + j0 + 2) = make_float2(v.z, v.w);
                        }
                    }
                }
            }
        }
    }
    if (tid < 50) sw[tid] = w5[g * 50 + tid];
    else if (tid < 68) sw[tid] = w3[g * 18 + (tid - 50)];
    __syncthreads();

    const float bias3 = b3[g], bias5 = b5[g];
    float* f3 = nullptr; long y3 = -1;
    float* f5 = nullptr; long y5 = -1;
    if (MODE == 0) {
        if (g < 128) f3 = &g_q[(bz * 128 + g) * HW];
        else         f3 = &g_k[(bz * 128 + (g - 128)) * HW];
        if (g < 64)  f5 = &g_k[(bz * 128 + 64 + g) * HW];
        else         y5 = (bz * 256 + (g - 64)) * HW;
    } else {
        y3 = (bz * 256 + 128 + g) * HW;
        y5 = (bz * 256 + 192 + g) * HW;
    }

#pragma unroll
    for (int half = 0; half < 2; half++) {
        float a3[2][4], a5[2][4];
#pragma unroll
        for (int i = 0; i < 2; i++)
#pragma unroll
            for (int j = 0; j < 4; j++) { a3[i][j] = 0.f; a5[i][j] = 0.f; }

#pragma unroll
        for (int ic = 0; ic < 2; ++ic) {
            // window starts at col px0 (float4-aligned): r[dy][dx] <-> gx = ox0+px0-2+dx
            const float* sc = s + ic * CONV_CH + (py0 + half * 2) * CONV_ROW + px0;
            float r[6][8];
#pragma unroll
            for (int dy = 0; dy < 6; dy++) {
                float4 w0 = *(const float4*)(sc + dy * CONV_ROW);
                float4 w1 = *(const float4*)(sc + dy * CONV_ROW + 4);
                r[dy][0] = w0.x; r[dy][1] = w0.y; r[dy][2] = w0.z; r[dy][3] = w0.w;
                r[dy][4] = w1.x; r[dy][5] = w1.y; r[dy][6] = w1.z; r[dy][7] = w1.w;
            }
            const float* w5s = sw + ic * 25;
#pragma unroll
            for (int t = 0; t < 25; t++) {
                float wv = w5s[t];
                int ky = t / 5, kx = t % 5;
#pragma unroll
                for (int oy = 0; oy < 2; oy++)
#pragma unroll
                    for (int ox = 0; ox < 4; ox++)
                        a5[oy][ox] += r[oy + ky][ox + kx] * wv;
            }
            const float* w3s = sw + 50 + ic * 9;
#pragma unroll
            for (int t = 0; t < 9; t++) {
                float wv = w3s[t];
                int ky = t / 3, kx = t % 3;
#pragma unroll
                for (int oy = 0; oy < 2; oy++)
#pragma unroll
                    for (int ox = 0; ox < 4; ox++)
                        a3[oy][ox] += r[oy + 1 + ky][ox + 1 + kx] * wv;
            }
        }

#pragma unroll
        for (int oy = 0; oy < 2; oy++) {
            int off = (oy0 + py0 + half * 2 + oy) * IMG + ox0 + px0;
#pragma unroll
            for (int ox = 0; ox < 4; ox++) {
                float v3 = a3[oy][ox] + bias3;
                float v5 = a5[oy][ox] + bias5;
                if (f3) f3[off + ox] = v3;
                else { __nv_bfloat16 h, l; split2(v3, h, l); g_yh[y3 + off + ox] = h; g_yl[y3 + off + ox] = l; }
                if (f5) f5[off + ox] = v5;
                else { __nv_bfloat16 h, l; split2(v5, h, l); g_yh[y5 + off + ox] = h; g_yl[y5 + off + ox] = l; }
            }
        }
    }
}

// ---------------- gram: per (b,h): G[16][16] = q @ k^T over pixels + sq norms ------
__global__ __launch_bounds__(256) void gram_k()
{
    const int bh = blockIdx.x;
    const int slice = blockIdx.y;
    const int b = bh >> 3, h = bh & 7;
    const float* qp = g_q + (long)(b * 128 + h * 16) * HW + slice * 1024;
    const float* kp = g_k + (long)(b * 128 + h * 16) * HW + slice * 1024;

    __shared__ float sq[64][17];
    __shared__ float sk[64][17];
    const int tid = threadIdx.x;
    const int phase = tid & 15, dg = (tid >> 4) & 3, eg = tid >> 6;

    float acc[4][4], aq[4], ak[4];
#pragma unroll
    for (int i = 0; i < 4; i++) {
        aq[i] = 0.f; ak[i] = 0.f;
#pragma unroll
        for (int j = 0; j < 4; j++) acc[i][j] = 0.f;
    }

    for (int blk = 0; blk < 16; ++blk) {
        for (int idx = tid; idx < 1024; idx += 256) {
            int d = idx >> 6, p = idx & 63;
            sq[p][d] = qp[(long)d * HW + blk * 64 + p];
            sk[p][d] = kp[(long)d * HW + blk * 64 + p];
        }
        __syncthreads();
        for (int p = phase; p < 64; p += 16) {
            float qv[4], kv[4];
#pragma unroll
            for (int i = 0; i < 4; i++) qv[i] = sq[p][dg * 4 + i];
#pragma unroll
            for (int j = 0; j < 4; j++) kv[j] = sk[p][eg * 4 + j];
#pragma unroll
            for (int i = 0; i < 4; i++)
#pragma unroll
                for (int j = 0; j < 4; j++) acc[i][j] += qv[i] * kv[j];
            if (eg == 0) {
#pragma unroll
                for (int i = 0; i < 4; i++) aq[i] += qv[i] * qv[i];
            }
            if (dg == 0) {
#pragma unroll
                for (int j = 0; j < 4; j++) ak[j] += kv[j] * kv[j];
            }
        }
        __syncthreads();
    }

    __shared__ float sG[288];
    for (int idx = tid; idx < 288; idx += 256) sG[idx] = 0.f;
    __syncthreads();
#pragma unroll
    for (int i = 0; i < 4; i++)
#pragma unroll
        for (int j = 0; j < 4; j++)
            atomicAdd(&sG[(dg * 4 + i) * 16 + eg * 4 + j], acc[i][j]);
    if (eg == 0) {
#pragma unroll
        for (int i = 0; i < 4; i++) atomicAdd(&sG[256 + dg * 4 + i], aq[i]);
    }
    if (dg == 0) {
#pragma unroll
        for (int j = 0; j < 4; j++) atomicAdd(&sG[272 + eg * 4 + j], ak[j]);
    }
    __syncthreads();
    float* gg = g_gram + bh * 288;
    for (int idx = tid; idx < 288; idx += 256) atomicAdd(gg + idx, sG[idx]);
}

// ---------------- attn: normalize gram, softmax, fold with proj into A (bf16 split) --
__global__ __launch_bounds__(256) void attn_k(
    const float* __restrict__ temp, const float* __restrict__ proj_w)
{
    const int b = blockIdx.x;
    const int part = blockIdx.y;
    const int tid = threadIdx.x;
    const long aBase = (long)b * 128 * 256;

    if (part == 8) {
        for (int idx = tid; idx < 128 * 128; idx += 256) {
            int c = idx >> 7, j = idx & 127;
            __nv_bfloat16 h, l;
            split2(proj_w[c * 256 + 128 + j], h, l);
            g_Ah[aBase + c * 256 + 128 + j] = h;
            g_Al[aBase + c * 256 + 128 + j] = l;
        }
        return;
    }
    const int h = part;
    const float* gg = g_gram + (b * 8 + h) * 288;
    __shared__ float sA[256], sqn[16], skn[16], srm[16], srs[16];
    if (tid < 16) {
        sqn[tid] = fmaxf(sqrtf(gg[256 + tid]), 1e-12f);
        skn[tid] = fmaxf(sqrtf(gg[272 + tid]), 1e-12f);
    }
    __syncthreads();
    const int d = tid >> 4, e = tid & 15;
    float val = gg[d * 16 + e] / (sqn[d] * skn[e]) * temp[h];
    sA[tid] = val;
    __syncthreads();
    if (e == 0) {
        float m = -1e30f;
        for (int j = 0; j < 16; j++) m = fmaxf(m, sA[d * 16 + j]);
        srm[d] = m;
    }
    __syncthreads();
    float p = expf(val - srm[d]);
    sA[tid] = p;
    __syncthreads();
    if (e == 0) {
        float ssum = 0.f;
        for (int j = 0; j < 16; j++) ssum += sA[d * 16 + j];
        srs[d] = ssum;
    }
    __syncthreads();
    sA[tid] = p / srs[d];
    __syncthreads();
    for (int o = tid; o < 2048; o += 256) {
        int c = o >> 4, ee = o & 15;
        float accv = 0.f;
#pragma unroll
        for (int dd = 0; dd < 16; dd++)
            accv += proj_w[c * 256 + h * 16 + dd] * sA[dd * 16 + ee];
        __nv_bfloat16 hh, ll;
        split2(accv, hh, ll);
        g_Ah[aBase + c * 256 + h * 16 + ee] = hh;
        g_Al[aBase + c * 256 + h * 16 + ee] = ll;
    }
}

// ---------------- launch ----------------
extern "C" void kernel_launch(void* const* d_in, const int* in_sizes, int n_in,
                              void* d_out, int out_size)
{
    const float* x      = (const float*)d_in[0];
    const float* pos_w  = (const float*)d_in[1];
    const float* pos_b  = (const float*)d_in[2];
    const float* qd3_w  = (const float*)d_in[3];
    const float* qd3_b  = (const float*)d_in[4];
    const float* qd5_w  = (const float*)d_in[5];
    const float* qd5_b  = (const float*)d_in[6];
    const float* temp   = (const float*)d_in[7];
    const float* d3_w   = (const float*)d_in[8];
    const float* d3_b   = (const float*)d_in[9];
    const float* d5_w   = (const float*)d_in[10];
    const float* d5_b   = (const float*)d_in[11];
    const float* proj_w = (const float*)d_in[12];
    float* out = (float*)d_out;

    zero_gram_k<<<72, 256>>>();
    convert_w_k<<<48, 256>>>(pos_w);
    k1_gemm<<<dim3(128, 6, 8), 128>>>(x, pos_b);
    dualconv_k<0><<<dim3(8, 192, 8), 128>>>(nullptr, qd3_w, qd3_b, qd5_w, qd5_b);
    dualconv_k<1><<<dim3(8, 64, 8), 128>>>(x, d3_w, d3_b, d5_w, d5_b);
    gram_k<<<dim3(64, 16), 256>>>();
    attn_k<<<dim3(8, 9), 256>>>(temp, proj_w);
    k4_gemm<<<dim3(128, 2, 8), 128>>>(out);
}

// round 15
// speedup vs baseline: 1.0376x; 1.0376x over previous
#include <cuda_runtime.h>
#include <cuda_bf16.h>
#include <cstdint>

#define HW 16384
#define IMG 128

// ---------------- scratch (static __device__, no allocs) ----------------
__device__ float g_t[8L * 384 * HW];            // pos-conv output (B,384,H,W) fp32
__device__ __nv_bfloat16 g_qb[8L * 128 * HW];   // q channels bf16 (gram-only consumer)
__device__ __nv_bfloat16 g_kb[8L * 128 * HW];   // k channels bf16 (gram-only consumer)
__device__ __nv_bfloat16 g_yh[8L * 256 * HW];   // [v|d3|d5] split hi
__device__ __nv_bfloat16 g_yl[8L * 256 * HW];   // [v|d3|d5] split lo
__device__ __nv_bfloat16 g_wh[384 * 128];       // pos_w split hi
__device__ __nv_bfloat16 g_wl[384 * 128];       // pos_w split lo
__device__ __nv_bfloat16 g_Ah[8 * 128 * 256];   // folded proj*attn split hi
__device__ __nv_bfloat16 g_Al[8 * 128 * 256];   // folded proj*attn split lo
__device__ float g_gram[64 * 288];              // per (b,h): G[256], qn[16], kn[16]

__device__ __forceinline__ void split2(float v, __nv_bfloat16& h, __nv_bfloat16& l) {
    h = __float2bfloat16(v);
    l = __float2bfloat16(v - __bfloat162float(h));
}
__device__ __forceinline__ uint32_t smem_u32(const void* p) {
    uint32_t a;
    asm("{ .reg .u64 t; cvta.to.shared.u64 t, %1; cvt.u32.u64 %0, t; }" : "=r"(a) : "l"(p));
    return a;
}
__device__ __forceinline__ uint32_t pack_bf2(__nv_bfloat16 a, __nv_bfloat16 b) {
    return (uint32_t)__bfloat16_as_ushort(a) | ((uint32_t)__bfloat16_as_ushort(b) << 16);
}

// ---------------- zero gram accumulators ----------------
__global__ void zero_gram_k() {
    int i = blockIdx.x * 256 + threadIdx.x;
    if (i < 64 * 288) g_gram[i] = 0.f;
}

// ---------------- split conversion for pos_w ----------------
__global__ void convert_w_k(const float* __restrict__ w) {
    long i = ((long)blockIdx.x * 256 + threadIdx.x) * 4;
    float4 v = *(const float4*)(w + i);
    __nv_bfloat16 h, l;
    split2(v.x, h, l); g_wh[i + 0] = h; g_wl[i + 0] = l;
    split2(v.y, h, l); g_wh[i + 1] = h; g_wl[i + 1] = l;
    split2(v.z, h, l); g_wh[i + 2] = h; g_wl[i + 2] = l;
    split2(v.w, h, l); g_wh[i + 3] = h; g_wl[i + 3] = l;
}

// ---------------- mma.sync helpers ----------------
__device__ __forceinline__ void hmma(float* c, const uint32_t* a, uint32_t b0, uint32_t b1) {
    asm volatile(
        "mma.sync.aligned.m16n8k16.row.col.f32.bf16.bf16.f32 "
        "{%0,%1,%2,%3}, {%4,%5,%6,%7}, {%8,%9}, {%0,%1,%2,%3};"
        : "+f"(c[0]), "+f"(c[1]), "+f"(c[2]), "+f"(c[3])
        : "r"(a[0]), "r"(a[1]), "r"(a[2]), "r"(a[3]), "r"(b0), "r"(b1));
}
__device__ __forceinline__ void ldsm4(uint32_t* r, uint32_t addr) {
    asm volatile("ldmatrix.sync.aligned.m8n8.x4.shared.b16 {%0,%1,%2,%3}, [%4];"
        : "=r"(r[0]), "=r"(r[1]), "=r"(r[2]), "=r"(r[3]) : "r"(addr));
}
__device__ __forceinline__ void ldsm4t(uint32_t* r, uint32_t addr) {
    asm volatile("ldmatrix.sync.aligned.m8n8.x4.trans.shared.b16 {%0,%1,%2,%3}, [%4];"
        : "=r"(r[0]), "=r"(r[1]), "=r"(r[2]), "=r"(r[3]) : "r"(addr));
}

// ---------------- bf16-split GEMM, register double-buffered ----------------
#define A_STRIDE 40
#define B_STRIDE 136

template <int K, bool BSPLIT>
__device__ __forceinline__ void mmasync_body(
    const __nv_bfloat16* __restrict__ Ah, const __nv_bfloat16* __restrict__ Al,
    long aStride,
    const __nv_bfloat16* __restrict__ Bh, const __nv_bfloat16* __restrict__ Bl,
    const float* __restrict__ Bf, long bStride,
    float* __restrict__ C, long cStride, const float* __restrict__ bias)
{
    __shared__ __nv_bfloat16 sAH[64 * A_STRIDE];
    __shared__ __nv_bfloat16 sAL[64 * A_STRIDE];
    __shared__ __nv_bfloat16 sBH[32 * B_STRIDE];
    __shared__ __nv_bfloat16 sBL[32 * B_STRIDE];
    const uint32_t uAH = smem_u32(sAH), uAL = smem_u32(sAL);
    const uint32_t uBH = smem_u32(sBH), uBL = smem_u32(sBL);

    const int b = blockIdx.z;
    const int m0 = blockIdx.y * 64;
    const int n0 = blockIdx.x * 128;
    const int tid = threadIdx.x;
    const int wid = tid >> 5, lane = tid & 31;
    const int wm = (wid & 1) * 32, wn = (wid >> 1) * 64;
    const int g = lane >> 2, tq = lane & 3;
    const int lrow = lane & 15;
    const int lcol = (lane >> 4) * 8;

    const __nv_bfloat16* AhB = Ah + (long)b * aStride;
    const __nv_bfloat16* AlB = Al + (long)b * aStride;
    const __nv_bfloat16* BhB = BSPLIT ? Bh + (long)b * bStride : nullptr;
    const __nv_bfloat16* BlB = BSPLIT ? Bl + (long)b * bStride : nullptr;
    const float* BfB = BSPLIT ? nullptr : Bf + (long)b * bStride;

    const int ar = tid >> 2, ac = (tid & 3) * 8;
    const int br4 = tid >> 4, bc4 = (tid & 15) * 8;
    const int brf = tid >> 5, bcf = (tid & 31) * 4;

    uint4 rA[2][2];
    uint4 rB[4][2];
    float4 rBF[8];

    auto ldg_chunk = [&](int ch) {
        const int ko = ch * 32;
#pragma unroll
        for (int p = 0; p < 2; p++) {
            long go = (long)(m0 + ar + p * 32) * K + ko + ac;
            rA[p][0] = *(const uint4*)(AhB + go);
            rA[p][1] = *(const uint4*)(AlB + go);
        }
        if (BSPLIT) {
#pragma unroll
            for (int p = 0; p < 4; p++) {
                long go = (long)(ko + br4 + p * 8) * HW + n0 + bc4;
                rB[p][0] = *(const uint4*)(BhB + go);
                rB[p][1] = *(const uint4*)(BlB + go);
            }
        } else {
#pragma unroll
            for (int p = 0; p < 8; p++) {
                long go = (long)(ko + brf + p * 4) * HW + n0 + bcf;
                rBF[p] = *(const float4*)(BfB + go);
            }
        }
    };

    auto sts_chunk = [&]() {
#pragma unroll
        for (int p = 0; p < 2; p++) {
            int row = ar + p * 32;
            *(uint4*)(sAH + row * A_STRIDE + ac) = rA[p][0];
            *(uint4*)(sAL + row * A_STRIDE + ac) = rA[p][1];
        }
        if (BSPLIT) {
#pragma unroll
            for (int p = 0; p < 4; p++) {
                int row = br4 + p * 8;
                *(uint4*)(sBH + row * B_STRIDE + bc4) = rB[p][0];
                *(uint4*)(sBL + row * B_STRIDE + bc4) = rB[p][1];
            }
        } else {
#pragma unroll
            for (int p = 0; p < 8; p++) {
                int row = brf + p * 4;
                float4 v = rBF[p];
                __nv_bfloat16 h0, l0, h1, l1, h2, l2, h3, l3;
                split2(v.x, h0, l0); split2(v.y, h1, l1);
                split2(v.z, h2, l2); split2(v.w, h3, l3);
                uint2 hp = make_uint2(pack_bf2(h0, h1), pack_bf2(h2, h3));
                uint2 lp = make_uint2(pack_bf2(l0, l1), pack_bf2(l2, l3));
                *(uint2*)(sBH + row * B_STRIDE + bcf) = hp;
                *(uint2*)(sBL + row * B_STRIDE + bcf) = lp;
            }
        }
    };

    float c[2][8][4];
#pragma unroll
    for (int mi = 0; mi < 2; mi++)
#pragma unroll
        for (int nb = 0; nb < 8; nb++)
#pragma unroll
            for (int j = 0; j < 4; j++) c[mi][nb][j] = 0.f;

    const int NC = K / 32;
    ldg_chunk(0);
    for (int ch = 0; ch < NC; ch++) {
        sts_chunk();
        __syncthreads();
        if (ch + 1 < NC) ldg_chunk(ch + 1);

#pragma unroll
        for (int kc = 0; kc < 2; kc++) {
            uint32_t aH[2][4], aL[2][4];
#pragma unroll
            for (int mi = 0; mi < 2; mi++) {
                uint32_t off = (uint32_t)(((wm + mi * 16 + lrow) * A_STRIDE + kc * 16 + lcol) * 2);
                ldsm4(aH[mi], uAH + off);
                ldsm4(aL[mi], uAL + off);
            }
#pragma unroll
            for (int nbp = 0; nbp < 4; nbp++) {
                uint32_t off = (uint32_t)(((kc * 16 + lrow) * B_STRIDE + wn + nbp * 16 + lcol) * 2);
                uint32_t bH[4], bL[4];
                ldsm4t(bH, uBH + off);
                ldsm4t(bL, uBL + off);
                int nb = nbp * 2;
#pragma unroll
                for (int t = 0; t < 3; t++) {
                    const uint32_t (*af)[4] = (t == 1) ? aL : aH;
                    const uint32_t* bf = (t == 2) ? bL : bH;
#pragma unroll
                    for (int mi = 0; mi < 2; mi++) {
                        hmma(c[mi][nb],     af[mi], bf[0], bf[1]);
                        hmma(c[mi][nb + 1], af[mi], bf[2], bf[3]);
                    }
                }
            }
        }
        __syncthreads();
    }

#pragma unroll
    for (int mi = 0; mi < 2; mi++) {
        int r0 = m0 + wm + mi * 16 + g;
        float bv0 = bias ? bias[r0] : 0.f;
        float bv1 = bias ? bias[r0 + 8] : 0.f;
#pragma unroll
        for (int nb = 0; nb < 8; nb++) {
            int col = n0 + wn + nb * 8 + tq * 2;
            float* p0 = C + (long)b * cStride + (long)r0 * HW + col;
            float* p1 = p0 + 8L * HW;
            *(float2*)p0 = make_float2(c[mi][nb][0] + bv0, c[mi][nb][1] + bv0);
            *(float2*)p1 = make_float2(c[mi][nb][2] + bv1, c[mi][nb][3] + bv1);
        }
    }
}

__global__ __launch_bounds__(128) void k1_gemm(const float* __restrict__ x,
                                               const float* __restrict__ pb) {
    mmasync_body<128, false>(g_wh, g_wl, 0L, nullptr, nullptr, x, 128L * HW,
                             g_t, 384L * HW, pb);
}
__global__ __launch_bounds__(128) void k4_gemm(float* __restrict__ out) {
    mmasync_body<256, true>(g_Ah, g_Al, 128L * 256, g_yh, g_yl, nullptr, 256L * HW,
                            out, 128L * HW, nullptr);
}

// ---------------- dual grouped conv (3x3 + 5x5 sharing input pair) ----------------
// R13 layout (measured best): 32x64 output per CTA, 128 threads, 6 CTAs/SM.
// Halo tile: 36 rows x 72 cols per channel; smem col j <-> gx = ox0 - 4 + j.
// q/k outputs stored as plain bf16 (gram is the only consumer; error ~3e-5).
#define CONV_ROW 72
#define CONV_CH (36 * CONV_ROW)

template <int MODE>
__global__ __launch_bounds__(128, 6) void dualconv_k(
    const float* __restrict__ in_ext,
    const float* __restrict__ w3, const float* __restrict__ b3,
    const float* __restrict__ w5, const float* __restrict__ b5)
{
    const int Cin = (MODE == 0) ? 384 : 128;
    const float* in = (MODE == 0) ? (const float*)g_t : in_ext;

    __shared__ float s[2 * CONV_CH];
    __shared__ float sw[68];

    const int tile = blockIdx.x;                 // 0..7: 4 row-tiles x 2 col-tiles
    const int oy0 = (tile >> 1) * 32;
    const int ox0 = (tile & 1) * 64;
    const int g = blockIdx.y;
    const long bz = blockIdx.z;
    const int tid = threadIdx.x;
    const int ttx = tid & 15, tty = tid >> 4;    // 16x8 threads, 4x4 px each
    const int py0 = tty * 4, px0 = ttx * 4;

    const float* in0 = in + (bz * Cin + 2 * g) * (long)HW;

    // ---- vectorized halo load: rows 0..35 (gy = oy0-2+row), cols 0..71 (gx = ox0-4+col)
    {
        const int lr = tid >> 4;     // 0..7: row within pass
        const int lc = tid & 15;     // chunk 0..15 (plus 16/17 for lc<2)
#pragma unroll
        for (int ch = 0; ch < 2; ch++) {
            const float* inc = in0 + ch * HW;
            float* sch = s + ch * CONV_CH;
#pragma unroll
            for (int rp = 0; rp < 40; rp += 8) {
                int r = rp + lr;
                if (r < 36) {
                    int gy = oy0 - 2 + r;
                    bool rowok = (unsigned)gy < 128u;
                    const float* rowp = inc + gy * IMG;
                    {
                        int gx0 = ox0 - 4 + lc * 4;
                        float4 v = make_float4(0.f, 0.f, 0.f, 0.f);
                        if (rowok && (unsigned)gx0 < 125u) v = *(const float4*)(rowp + gx0);
                        *(float4*)(sch + r * CONV_ROW + lc * 4) = v;
                    }
                    if (lc < 2) {
                        int j = 16 + lc;
                        int gx0 = ox0 - 4 + j * 4;
                        float4 v = make_float4(0.f, 0.f, 0.f, 0.f);
                        if (rowok && (unsigned)gx0 < 125u) v = *(const float4*)(rowp + gx0);
                        *(float4*)(sch + r * CONV_ROW + j * 4) = v;
                    }
                }
            }
        }
    }
    if (tid < 50) sw[tid] = w5[g * 50 + tid];
    else if (tid < 68) sw[tid] = w3[g * 18 + (tid - 50)];
    __syncthreads();

    const float bias3 = b3[g], bias5 = b5[g];
    __nv_bfloat16* bf3 = nullptr; long y3 = -1;
    __nv_bfloat16* bf5 = nullptr; long y5 = -1;
    if (MODE == 0) {
        if (g < 128) bf3 = &g_qb[(bz * 128 + g) * HW];
        else         bf3 = &g_kb[(bz * 128 + (g - 128)) * HW];
        if (g < 64)  bf5 = &g_kb[(bz * 128 + 64 + g) * HW];
        else         y5 = (bz * 256 + (g - 64)) * HW;
    } else {
        y3 = (bz * 256 + 128 + g) * HW;
        y5 = (bz * 256 + 192 + g) * HW;
    }

#pragma unroll
    for (int half = 0; half < 2; half++) {
        float a3[2][4], a5[2][4];
#pragma unroll
        for (int i = 0; i < 2; i++)
#pragma unroll
            for (int j = 0; j < 4; j++) { a3[i][j] = 0.f; a5[i][j] = 0.f; }

#pragma unroll
        for (int ic = 0; ic < 2; ++ic) {
            const float* sc = s + ic * CONV_CH + (py0 + half * 2) * CONV_ROW + px0 + 2;
            float r[6][8];
#pragma unroll
            for (int dy = 0; dy < 6; dy++)
#pragma unroll
                for (int dx = 0; dx < 8; dx++) r[dy][dx] = sc[dy * CONV_ROW + dx];
            const float* w5s = sw + ic * 25;
#pragma unroll
            for (int t = 0; t < 25; t++) {
                float wv = w5s[t];
                int ky = t / 5, kx = t % 5;
#pragma unroll
                for (int oy = 0; oy < 2; oy++)
#pragma unroll
                    for (int ox = 0; ox < 4; ox++)
                        a5[oy][ox] += r[oy + ky][ox + kx] * wv;
            }
            const float* w3s = sw + 50 + ic * 9;
#pragma unroll
            for (int t = 0; t < 9; t++) {
                float wv = w3s[t];
                int ky = t / 3, kx = t % 3;
#pragma unroll
                for (int oy = 0; oy < 2; oy++)
#pragma unroll
                    for (int ox = 0; ox < 4; ox++)
                        a3[oy][ox] += r[oy + 1 + ky][ox + 1 + kx] * wv;
            }
        }

#pragma unroll
        for (int oy = 0; oy < 2; oy++) {
            int off = (oy0 + py0 + half * 2 + oy) * IMG + ox0 + px0;
#pragma unroll
            for (int ox = 0; ox < 4; ox++) {
                float v3 = a3[oy][ox] + bias3;
                float v5 = a5[oy][ox] + bias5;
                if (bf3) bf3[off + ox] = __float2bfloat16(v3);
                else { __nv_bfloat16 h, l; split2(v3, h, l); g_yh[y3 + off + ox] = h; g_yl[y3 + off + ox] = l; }
                if (bf5) bf5[off + ox] = __float2bfloat16(v5);
                else { __nv_bfloat16 h, l; split2(v5, h, l); g_yh[y5 + off + ox] = h; g_yl[y5 + off + ox] = l; }
            }
        }
    }
}

// ---------------- gram: per (b,h): G[16][16] = q @ k^T over pixels + sq norms ------
// q/k now bf16 in global; converted to fp32 in smem, reduction math unchanged.
__global__ __launch_bounds__(256) void gram_k()
{
    const int bh = blockIdx.x;
    const int slice = blockIdx.y;
    const int b = bh >> 3, h = bh & 7;
    const __nv_bfloat16* qp = g_qb + (long)(b * 128 + h * 16) * HW + slice * 1024;
    const __nv_bfloat16* kp = g_kb + (long)(b * 128 + h * 16) * HW + slice * 1024;

    __shared__ float sq[64][17];
    __shared__ float sk[64][17];
    const int tid = threadIdx.x;
    const int phase = tid & 15, dg = (tid >> 4) & 3, eg = tid >> 6;

    float acc[4][4], aq[4], ak[4];
#pragma unroll
    for (int i = 0; i < 4; i++) {
        aq[i] = 0.f; ak[i] = 0.f;
#pragma unroll
        for (int j = 0; j < 4; j++) acc[i][j] = 0.f;
    }

    for (int blk = 0; blk < 16; ++blk) {
        for (int idx = tid; idx < 1024; idx += 256) {
            int d = idx >> 6, p = idx & 63;
            sq[p][d] = __bfloat162float(qp[(long)d * HW + blk * 64 + p]);
            sk[p][d] = __bfloat162float(kp[(long)d * HW + blk * 64 + p]);
        }
        __syncthreads();
        for (int p = phase; p < 64; p += 16) {
            float qv[4], kv[4];
#pragma unroll
            for (int i = 0; i < 4; i++) qv[i] = sq[p][dg * 4 + i];
#pragma unroll
            for (int j = 0; j < 4; j++) kv[j] = sk[p][eg * 4 + j];
#pragma unroll
            for (int i = 0; i < 4; i++)
#pragma unroll
                for (int j = 0; j < 4; j++) acc[i][j] += qv[i] * kv[j];
            if (eg == 0) {
#pragma unroll
                for (int i = 0; i < 4; i++) aq[i] += qv[i] * qv[i];
            }
            if (dg == 0) {
#pragma unroll
                for (int j = 0; j < 4; j++) ak[j] += kv[j] * kv[j];
            }
        }
        __syncthreads();
    }

    __shared__ float sG[288];
    for (int idx = tid; idx < 288; idx += 256) sG[idx] = 0.f;
    __syncthreads();
#pragma unroll
    for (int i = 0; i < 4; i++)
#pragma unroll
        for (int j = 0; j < 4; j++)
            atomicAdd(&sG[(dg * 4 + i) * 16 + eg * 4 + j], acc[i][j]);
    if (eg == 0) {
#pragma unroll
        for (int i = 0; i < 4; i++) atomicAdd(&sG[256 + dg * 4 + i], aq[i]);
    }
    if (dg == 0) {
#pragma unroll
        for (int j = 0; j < 4; j++) atomicAdd(&sG[272 + eg * 4 + j], ak[j]);
    }
    __syncthreads();
    float* gg = g_gram + bh * 288;
    for (int idx = tid; idx < 288; idx += 256) atomicAdd(gg + idx, sG[idx]);
}

// ---------------- attn: normalize gram, softmax, fold with proj into A (bf16 split) --
__global__ __launch_bounds__(256) void attn_k(
    const float* __restrict__ temp, const float* __restrict__ proj_w)
{
    const int b = blockIdx.x;
    const int part = blockIdx.y;
    const int tid = threadIdx.x;
    const long aBase = (long)b * 128 * 256;

    if (part == 8) {
        for (int idx = tid; idx < 128 * 128; idx += 256) {
            int c = idx >> 7, j = idx & 127;
            __nv_bfloat16 h, l;
            split2(proj_w[c * 256 + 128 + j], h, l);
            g_Ah[aBase + c * 256 + 128 + j] = h;
            g_Al[aBase + c * 256 + 128 + j] = l;
        }
        return;
    }
    const int h = part;
    const float* gg = g_gram + (b * 8 + h) * 288;
    __shared__ float sA[256], sqn[16], skn[16], srm[16], srs[16];
    if (tid < 16) {
        sqn[tid] = fmaxf(sqrtf(gg[256 + tid]), 1e-12f);
        skn[tid] = fmaxf(sqrtf(gg[272 + tid]), 1e-12f);
    }
    __syncthreads();
    const int d = tid >> 4, e = tid & 15;
    float val = gg[d * 16 + e] / (sqn[d] * skn[e]) * temp[h];
    sA[tid] = val;
    __syncthreads();
    if (e == 0) {
        float m = -1e30f;
        for (int j = 0; j < 16; j++) m = fmaxf(m, sA[d * 16 + j]);
        srm[d] = m;
    }
    __syncthreads();
    float p = expf(val - srm[d]);
    sA[tid] = p;
    __syncthreads();
    if (e == 0) {
        float ssum = 0.f;
        for (int j = 0; j < 16; j++) ssum += sA[d * 16 + j];
        srs[d] = ssum;
    }
    __syncthreads();
    sA[tid] = p / srs[d];
    __syncthreads();
    for (int o = tid; o < 2048; o += 256) {
        int c = o >> 4, ee = o & 15;
        float accv = 0.f;
#pragma unroll
        for (int dd = 0; dd < 16; dd++)
            accv += proj_w[c * 256 + h * 16 + dd] * sA[dd * 16 + ee];
        __nv_bfloat16 hh, ll;
        split2(accv, hh, ll);
        g_Ah[aBase + c * 256 + h * 16 + ee] = hh;
        g_Al[aBase + c * 256 + h * 16 + ee] = ll;
    }
}

// ---------------- launch ----------------
extern "C" void kernel_launch(void* const* d_in, const int* in_sizes, int n_in,
                              void* d_out, int out_size)
{
    const float* x      = (const float*)d_in[0];
    const float* pos_w  = (const float*)d_in[1];
    const float* pos_b  = (const float*)d_in[2];
    const float* qd3_w  = (const float*)d_in[3];
    const float* qd3_b  = (const float*)d_in[4];
    const float* qd5_w  = (const float*)d_in[5];
    const float* qd5_b  = (const float*)d_in[6];
    const float* temp   = (const float*)d_in[7];
    const float* d3_w   = (const float*)d_in[8];
    const float* d3_b   = (const float*)d_in[9];
    const float* d5_w   = (const float*)d_in[10];
    const float* d5_b   = (const float*)d_in[11];
    const float* proj_w = (const float*)d_in[12];
    float* out = (float*)d_out;

    zero_gram_k<<<72, 256>>>();
    convert_w_k<<<48, 256>>>(pos_w);
    k1_gemm<<<dim3(128, 6, 8), 128>>>(x, pos_b);
    dualconv_k<0><<<dim3(8, 192, 8), 128>>>(nullptr, qd3_w, qd3_b, qd5_w, qd5_b);
    dualconv_k<1><<<dim3(8, 64, 8), 128>>>(x, d3_w, d3_b, d5_w, d5_b);
    gram_k<<<dim3(64, 16), 256>>>();
    attn_k<<<dim3(8, 9), 256>>>(temp, proj_w);
    k4_gemm<<<dim3(128, 2, 8), 128>>>(out);
}

// round 16
// speedup vs baseline: 1.1771x; 1.1344x over previous
#include <cuda_runtime.h>
#include <cuda_bf16.h>
#include <cstdint>

#define HW 16384
#define IMG 128

// ---------------- scratch (static __device__, no allocs) ----------------
__device__ float g_t[8L * 384 * HW];            // pos-conv output (B,384,H,W) fp32
__device__ __nv_bfloat16 g_qb[8L * 128 * HW];   // q channels bf16 (gram-only consumer)
__device__ __nv_bfloat16 g_kb[8L * 128 * HW];   // k channels bf16 (gram-only consumer)
__device__ __nv_bfloat16 g_yh[8L * 256 * HW];   // [v|d3|d5] split hi
__device__ __nv_bfloat16 g_yl[8L * 256 * HW];   // [v|d3|d5] split lo
__device__ __nv_bfloat16 g_wh[384 * 128];       // pos_w split hi
__device__ __nv_bfloat16 g_wl[384 * 128];       // pos_w split lo
__device__ __nv_bfloat16 g_Ah[8 * 128 * 256];   // folded proj*attn split hi
__device__ __nv_bfloat16 g_Al[8 * 128 * 256];   // folded proj*attn split lo
__device__ float g_gram[64 * 288];              // per (b,h): G[256], qn[16], kn[16]

__device__ __forceinline__ void split2(float v, __nv_bfloat16& h, __nv_bfloat16& l) {
    h = __float2bfloat16(v);
    l = __float2bfloat16(v - __bfloat162float(h));
}
__device__ __forceinline__ uint32_t smem_u32(const void* p) {
    uint32_t a;
    asm("{ .reg .u64 t; cvta.to.shared.u64 t, %1; cvt.u32.u64 %0, t; }" : "=r"(a) : "l"(p));
    return a;
}
__device__ __forceinline__ uint32_t pack_bf2(__nv_bfloat16 a, __nv_bfloat16 b) {
    return (uint32_t)__bfloat16_as_ushort(a) | ((uint32_t)__bfloat16_as_ushort(b) << 16);
}
__device__ __forceinline__ uint2 pack_bf4(float a, float b, float c, float d) {
    return make_uint2(pack_bf2(__float2bfloat16(a), __float2bfloat16(b)),
                      pack_bf2(__float2bfloat16(c), __float2bfloat16(d)));
}

// ---------------- zero gram accumulators ----------------
__global__ void zero_gram_k() {
    int i = blockIdx.x * 256 + threadIdx.x;
    if (i < 64 * 288) g_gram[i] = 0.f;
}

// ---------------- split conversion for pos_w ----------------
__global__ void convert_w_k(const float* __restrict__ w) {
    long i = ((long)blockIdx.x * 256 + threadIdx.x) * 4;
    float4 v = *(const float4*)(w + i);
    __nv_bfloat16 h, l;
    split2(v.x, h, l); g_wh[i + 0] = h; g_wl[i + 0] = l;
    split2(v.y, h, l); g_wh[i + 1] = h; g_wl[i + 1] = l;
    split2(v.z, h, l); g_wh[i + 2] = h; g_wl[i + 2] = l;
    split2(v.w, h, l); g_wh[i + 3] = h; g_wl[i + 3] = l;
}

// ---------------- mma.sync helpers ----------------
__device__ __forceinline__ void hmma(float* c, const uint32_t* a, uint32_t b0, uint32_t b1) {
    asm volatile(
        "mma.sync.aligned.m16n8k16.row.col.f32.bf16.bf16.f32 "
        "{%0,%1,%2,%3}, {%4,%5,%6,%7}, {%8,%9}, {%0,%1,%2,%3};"
        : "+f"(c[0]), "+f"(c[1]), "+f"(c[2]), "+f"(c[3])
        : "r"(a[0]), "r"(a[1]), "r"(a[2]), "r"(a[3]), "r"(b0), "r"(b1));
}
__device__ __forceinline__ void ldsm4(uint32_t* r, uint32_t addr) {
    asm volatile("ldmatrix.sync.aligned.m8n8.x4.shared.b16 {%0,%1,%2,%3}, [%4];"
        : "=r"(r[0]), "=r"(r[1]), "=r"(r[2]), "=r"(r[3]) : "r"(addr));
}
__device__ __forceinline__ void ldsm4t(uint32_t* r, uint32_t addr) {
    asm volatile("ldmatrix.sync.aligned.m8n8.x4.trans.shared.b16 {%0,%1,%2,%3}, [%4];"
        : "=r"(r[0]), "=r"(r[1]), "=r"(r[2]), "=r"(r[3]) : "r"(addr));
}

// ---------------- bf16-split GEMM, register double-buffered ----------------
#define A_STRIDE 40
#define B_STRIDE 136

template <int K, bool BSPLIT>
__device__ __forceinline__ void mmasync_body(
    const __nv_bfloat16* __restrict__ Ah, const __nv_bfloat16* __restrict__ Al,
    long aStride,
    const __nv_bfloat16* __restrict__ Bh, const __nv_bfloat16* __restrict__ Bl,
    const float* __restrict__ Bf, long bStride,
    float* __restrict__ C, long cStride, const float* __restrict__ bias)
{
    __shared__ __nv_bfloat16 sAH[64 * A_STRIDE];
    __shared__ __nv_bfloat16 sAL[64 * A_STRIDE];
    __shared__ __nv_bfloat16 sBH[32 * B_STRIDE];
    __shared__ __nv_bfloat16 sBL[32 * B_STRIDE];
    const uint32_t uAH = smem_u32(sAH), uAL = smem_u32(sAL);
    const uint32_t uBH = smem_u32(sBH), uBL = smem_u32(sBL);

    const int b = blockIdx.z;
    const int m0 = blockIdx.y * 64;
    const int n0 = blockIdx.x * 128;
    const int tid = threadIdx.x;
    const int wid = tid >> 5, lane = tid & 31;
    const int wm = (wid & 1) * 32, wn = (wid >> 1) * 64;
    const int g = lane >> 2, tq = lane & 3;
    const int lrow = lane & 15;
    const int lcol = (lane >> 4) * 8;

    const __nv_bfloat16* AhB = Ah + (long)b * aStride;
    const __nv_bfloat16* AlB = Al + (long)b * aStride;
    const __nv_bfloat16* BhB = BSPLIT ? Bh + (long)b * bStride : nullptr;
    const __nv_bfloat16* BlB = BSPLIT ? Bl + (long)b * bStride : nullptr;
    const float* BfB = BSPLIT ? nullptr : Bf + (long)b * bStride;

    const int ar = tid >> 2, ac = (tid & 3) * 8;
    const int br4 = tid >> 4, bc4 = (tid & 15) * 8;
    const int brf = tid >> 5, bcf = (tid & 31) * 4;

    uint4 rA[2][2];
    uint4 rB[4][2];
    float4 rBF[8];

    auto ldg_chunk = [&](int ch) {
        const int ko = ch * 32;
#pragma unroll
        for (int p = 0; p < 2; p++) {
            long go = (long)(m0 + ar + p * 32) * K + ko + ac;
            rA[p][0] = *(const uint4*)(AhB + go);
            rA[p][1] = *(const uint4*)(AlB + go);
        }
        if (BSPLIT) {
#pragma unroll
            for (int p = 0; p < 4; p++) {
                long go = (long)(ko + br4 + p * 8) * HW + n0 + bc4;
                rB[p][0] = *(const uint4*)(BhB + go);
                rB[p][1] = *(const uint4*)(BlB + go);
            }
        } else {
#pragma unroll
            for (int p = 0; p < 8; p++) {
                long go = (long)(ko + brf + p * 4) * HW + n0 + bcf;
                rBF[p] = *(const float4*)(BfB + go);
            }
        }
    };

    auto sts_chunk = [&]() {
#pragma unroll
        for (int p = 0; p < 2; p++) {
            int row = ar + p * 32;
            *(uint4*)(sAH + row * A_STRIDE + ac) = rA[p][0];
            *(uint4*)(sAL + row * A_STRIDE + ac) = rA[p][1];
        }
        if (BSPLIT) {
#pragma unroll
            for (int p = 0; p < 4; p++) {
                int row = br4 + p * 8;
                *(uint4*)(sBH + row * B_STRIDE + bc4) = rB[p][0];
                *(uint4*)(sBL + row * B_STRIDE + bc4) = rB[p][1];
            }
        } else {
#pragma unroll
            for (int p = 0; p < 8; p++) {
                int row = brf + p * 4;
                float4 v = rBF[p];
                __nv_bfloat16 h0, l0, h1, l1, h2, l2, h3, l3;
                split2(v.x, h0, l0); split2(v.y, h1, l1);
                split2(v.z, h2, l2); split2(v.w, h3, l3);
                uint2 hp = make_uint2(pack_bf2(h0, h1), pack_bf2(h2, h3));
                uint2 lp = make_uint2(pack_bf2(l0, l1), pack_bf2(l2, l3));
                *(uint2*)(sBH + row * B_STRIDE + bcf) = hp;
                *(uint2*)(sBL + row * B_STRIDE + bcf) = lp;
            }
        }
    };

    float c[2][8][4];
#pragma unroll
    for (int mi = 0; mi < 2; mi++)
#pragma unroll
        for (int nb = 0; nb < 8; nb++)
#pragma unroll
            for (int j = 0; j < 4; j++) c[mi][nb][j] = 0.f;

    const int NC = K / 32;
    ldg_chunk(0);
    for (int ch = 0; ch < NC; ch++) {
        sts_chunk();
        __syncthreads();
        if (ch + 1 < NC) ldg_chunk(ch + 1);

#pragma unroll
        for (int kc = 0; kc < 2; kc++) {
            uint32_t aH[2][4], aL[2][4];
#pragma unroll
            for (int mi = 0; mi < 2; mi++) {
                uint32_t off = (uint32_t)(((wm + mi * 16 + lrow) * A_STRIDE + kc * 16 + lcol) * 2);
                ldsm4(aH[mi], uAH + off);
                ldsm4(aL[mi], uAL + off);
            }
#pragma unroll
            for (int nbp = 0; nbp < 4; nbp++) {
                uint32_t off = (uint32_t)(((kc * 16 + lrow) * B_STRIDE + wn + nbp * 16 + lcol) * 2);
                uint32_t bH[4], bL[4];
                ldsm4t(bH, uBH + off);
                ldsm4t(bL, uBL + off);
                int nb = nbp * 2;
#pragma unroll
                for (int t = 0; t < 3; t++) {
                    const uint32_t (*af)[4] = (t == 1) ? aL : aH;
                    const uint32_t* bf = (t == 2) ? bL : bH;
#pragma unroll
                    for (int mi = 0; mi < 2; mi++) {
                        hmma(c[mi][nb],     af[mi], bf[0], bf[1]);
                        hmma(c[mi][nb + 1], af[mi], bf[2], bf[3]);
                    }
                }
            }
        }
        __syncthreads();
    }

#pragma unroll
    for (int mi = 0; mi < 2; mi++) {
        int r0 = m0 + wm + mi * 16 + g;
        float bv0 = bias ? bias[r0] : 0.f;
        float bv1 = bias ? bias[r0 + 8] : 0.f;
#pragma unroll
        for (int nb = 0; nb < 8; nb++) {
            int col = n0 + wn + nb * 8 + tq * 2;
            float* p0 = C + (long)b * cStride + (long)r0 * HW + col;
            float* p1 = p0 + 8L * HW;
            *(float2*)p0 = make_float2(c[mi][nb][0] + bv0, c[mi][nb][1] + bv0);
            *(float2*)p1 = make_float2(c[mi][nb][2] + bv1, c[mi][nb][3] + bv1);
        }
    }
}

__global__ __launch_bounds__(128) void k1_gemm(const float* __restrict__ x,
                                               const float* __restrict__ pb) {
    mmasync_body<128, false>(g_wh, g_wl, 0L, nullptr, nullptr, x, 128L * HW,
                             g_t, 384L * HW, pb);
}
__global__ __launch_bounds__(128) void k4_gemm(float* __restrict__ out) {
    mmasync_body<256, true>(g_Ah, g_Al, 128L * 256, g_yh, g_yl, nullptr, 256L * HW,
                            out, 128L * HW, nullptr);
}

// ---------------- dual grouped conv (3x3 + 5x5 sharing input pair) ----------------
// R13 layout: 32x64 output per CTA, 128 threads, 6 CTAs/SM.
// Epilogue stores vectorized: 4 px -> one uint2 (4 bf16) per output stream.
#define CONV_ROW 72
#define CONV_CH (36 * CONV_ROW)

template <int MODE>
__global__ __launch_bounds__(128, 6) void dualconv_k(
    const float* __restrict__ in_ext,
    const float* __restrict__ w3, const float* __restrict__ b3,
    const float* __restrict__ w5, const float* __restrict__ b5)
{
    const int Cin = (MODE == 0) ? 384 : 128;
    const float* in = (MODE == 0) ? (const float*)g_t : in_ext;

    __shared__ float s[2 * CONV_CH];
    __shared__ float sw[68];

    const int tile = blockIdx.x;                 // 0..7: 4 row-tiles x 2 col-tiles
    const int oy0 = (tile >> 1) * 32;
    const int ox0 = (tile & 1) * 64;
    const int g = blockIdx.y;
    const long bz = blockIdx.z;
    const int tid = threadIdx.x;
    const int ttx = tid & 15, tty = tid >> 4;    // 16x8 threads, 4x4 px each
    const int py0 = tty * 4, px0 = ttx * 4;

    const float* in0 = in + (bz * Cin + 2 * g) * (long)HW;

    // ---- vectorized halo load: rows 0..35 (gy = oy0-2+row), cols 0..71 (gx = ox0-4+col)
    {
        const int lr = tid >> 4;
        const int lc = tid & 15;
#pragma unroll
        for (int ch = 0; ch < 2; ch++) {
            const float* inc = in0 + ch * HW;
            float* sch = s + ch * CONV_CH;
#pragma unroll
            for (int rp = 0; rp < 40; rp += 8) {
                int r = rp + lr;
                if (r < 36) {
                    int gy = oy0 - 2 + r;
                    bool rowok = (unsigned)gy < 128u;
                    const float* rowp = inc + gy * IMG;
                    {
                        int gx0 = ox0 - 4 + lc * 4;
                        float4 v = make_float4(0.f, 0.f, 0.f, 0.f);
                        if (rowok && (unsigned)gx0 < 125u) v = *(const float4*)(rowp + gx0);
                        *(float4*)(sch + r * CONV_ROW + lc * 4) = v;
                    }
                    if (lc < 2) {
                        int j = 16 + lc;
                        int gx0 = ox0 - 4 + j * 4;
                        float4 v = make_float4(0.f, 0.f, 0.f, 0.f);
                        if (rowok && (unsigned)gx0 < 125u) v = *(const float4*)(rowp + gx0);
                        *(float4*)(sch + r * CONV_ROW + j * 4) = v;
                    }
                }
            }
        }
    }
    if (tid < 50) sw[tid] = w5[g * 50 + tid];
    else if (tid < 68) sw[tid] = w3[g * 18 + (tid - 50)];
    __syncthreads();

    const float bias3 = b3[g], bias5 = b5[g];
    __nv_bfloat16* bf3 = nullptr; long y3 = -1;
    __nv_bfloat16* bf5 = nullptr; long y5 = -1;
    if (MODE == 0) {
        if (g < 128) bf3 = &g_qb[(bz * 128 + g) * HW];
        else         bf3 = &g_kb[(bz * 128 + (g - 128)) * HW];
        if (g < 64)  bf5 = &g_kb[(bz * 128 + 64 + g) * HW];
        else         y5 = (bz * 256 + (g - 64)) * HW;
    } else {
        y3 = (bz * 256 + 128 + g) * HW;
        y5 = (bz * 256 + 192 + g) * HW;
    }

#pragma unroll
    for (int half = 0; half < 2; half++) {
        float a3[2][4], a5[2][4];
#pragma unroll
        for (int i = 0; i < 2; i++)
#pragma unroll
            for (int j = 0; j < 4; j++) { a3[i][j] = 0.f; a5[i][j] = 0.f; }

#pragma unroll
        for (int ic = 0; ic < 2; ++ic) {
            const float* sc = s + ic * CONV_CH + (py0 + half * 2) * CONV_ROW + px0 + 2;
            float r[6][8];
#pragma unroll
            for (int dy = 0; dy < 6; dy++)
#pragma unroll
                for (int dx = 0; dx < 8; dx++) r[dy][dx] = sc[dy * CONV_ROW + dx];
            const float* w5s = sw + ic * 25;
#pragma unroll
            for (int t = 0; t < 25; t++) {
                float wv = w5s[t];
                int ky = t / 5, kx = t % 5;
#pragma unroll
                for (int oy = 0; oy < 2; oy++)
#pragma unroll
                    for (int ox = 0; ox < 4; ox++)
                        a5[oy][ox] += r[oy + ky][ox + kx] * wv;
            }
            const float* w3s = sw + 50 + ic * 9;
#pragma unroll
            for (int t = 0; t < 9; t++) {
                float wv = w3s[t];
                int ky = t / 3, kx = t % 3;
#pragma unroll
                for (int oy = 0; oy < 2; oy++)
#pragma unroll
                    for (int ox = 0; ox < 4; ox++)
                        a3[oy][ox] += r[oy + 1 + ky][ox + 1 + kx] * wv;
            }
        }

#pragma unroll
        for (int oy = 0; oy < 2; oy++) {
            int off = (oy0 + py0 + half * 2 + oy) * IMG + ox0 + px0;
            float v30 = a3[oy][0] + bias3, v31 = a3[oy][1] + bias3;
            float v32 = a3[oy][2] + bias3, v33 = a3[oy][3] + bias3;
            float v50 = a5[oy][0] + bias5, v51 = a5[oy][1] + bias5;
            float v52 = a5[oy][2] + bias5, v53 = a5[oy][3] + bias5;
            if (bf3) {
                *(uint2*)(bf3 + off) = pack_bf4(v30, v31, v32, v33);
            } else {
                __nv_bfloat16 h0, l0, h1, l1, h2, l2, h3, l3;
                split2(v30, h0, l0); split2(v31, h1, l1);
                split2(v32, h2, l2); split2(v33, h3, l3);
                *(uint2*)(g_yh + y3 + off) = make_uint2(pack_bf2(h0, h1), pack_bf2(h2, h3));
                *(uint2*)(g_yl + y3 + off) = make_uint2(pack_bf2(l0, l1), pack_bf2(l2, l3));
            }
            if (bf5) {
                *(uint2*)(bf5 + off) = pack_bf4(v50, v51, v52, v53);
            } else {
                __nv_bfloat16 h0, l0, h1, l1, h2, l2, h3, l3;
                split2(v50, h0, l0); split2(v51, h1, l1);
                split2(v52, h2, l2); split2(v53, h3, l3);
                *(uint2*)(g_yh + y5 + off) = make_uint2(pack_bf2(h0, h1), pack_bf2(h2, h3));
                *(uint2*)(g_yl + y5 + off) = make_uint2(pack_bf2(l0, l1), pack_bf2(l2, l3));
            }
        }
    }
}

// ---------------- gram: per (b,h): G[16][16] = q @ k^T over pixels + sq norms ------
// q/k bf16 in global; vectorized uint2 loads (4 bf16), fp32 reduction unchanged.
__global__ __launch_bounds__(256) void gram_k()
{
    const int bh = blockIdx.x;
    const int slice = blockIdx.y;
    const int b = bh >> 3, h = bh & 7;
    const __nv_bfloat16* qp = g_qb + (long)(b * 128 + h * 16) * HW + slice * 1024;
    const __nv_bfloat16* kp = g_kb + (long)(b * 128 + h * 16) * HW + slice * 1024;

    __shared__ float sq[64][17];
    __shared__ float sk[64][17];
    const int tid = threadIdx.x;
    const int phase = tid & 15, dg = (tid >> 4) & 3, eg = tid >> 6;
    const int ld_d = tid >> 4, ld_p = (tid & 15) * 4;   // 16 d x 16 p-quads

    float acc[4][4], aq[4], ak[4];
#pragma unroll
    for (int i = 0; i < 4; i++) {
        aq[i] = 0.f; ak[i] = 0.f;
#pragma unroll
        for (int j = 0; j < 4; j++) acc[i][j] = 0.f;
    }

    for (int blk = 0; blk < 16; ++blk) {
        {
            uint2 vq = *(const uint2*)(qp + (long)ld_d * HW + blk * 64 + ld_p);
            uint2 vk = *(const uint2*)(kp + (long)ld_d * HW + blk * 64 + ld_p);
            __nv_bfloat16 t0, t1;
            t0 = __ushort_as_bfloat16((unsigned short)(vq.x & 0xFFFF));
            t1 = __ushort_as_bfloat16((unsigned short)(vq.x >> 16));
            sq[ld_p + 0][ld_d] = __bfloat162float(t0);
            sq[ld_p + 1][ld_d] = __bfloat162float(t1);
            t0 = __ushort_as_bfloat16((unsigned short)(vq.y & 0xFFFF));
            t1 = __ushort_as_bfloat16((unsigned short)(vq.y >> 16));
            sq[ld_p + 2][ld_d] = __bfloat162float(t0);
            sq[ld_p + 3][ld_d] = __bfloat162float(t1);
            t0 = __ushort_as_bfloat16((unsigned short)(vk.x & 0xFFFF));
            t1 = __ushort_as_bfloat16((unsigned short)(vk.x >> 16));
            sk[ld_p + 0][ld_d] = __bfloat162float(t0);
            sk[ld_p + 1][ld_d] = __bfloat162float(t1);
            t0 = __ushort_as_bfloat16((unsigned short)(vk.y & 0xFFFF));
            t1 = __ushort_as_bfloat16((unsigned short)(vk.y >> 16));
            sk[ld_p + 2][ld_d] = __bfloat162float(t0);
            sk[ld_p + 3][ld_d] = __bfloat162float(t1);
        }
        __syncthreads();
        for (int p = phase; p < 64; p += 16) {
            float qv[4], kv[4];
#pragma unroll
            for (int i = 0; i < 4; i++) qv[i] = sq[p][dg * 4 + i];
#pragma unroll
            for (int j = 0; j < 4; j++) kv[j] = sk[p][eg * 4 + j];
#pragma unroll
            for (int i = 0; i < 4; i++)
#pragma unroll
                for (int j = 0; j < 4; j++) acc[i][j] += qv[i] * kv[j];
            if (eg == 0) {
#pragma unroll
                for (int i = 0; i < 4; i++) aq[i] += qv[i] * qv[i];
            }
            if (dg == 0) {
#pragma unroll
                for (int j = 0; j < 4; j++) ak[j] += kv[j] * kv[j];
            }
        }
        __syncthreads();
    }

    __shared__ float sG[288];
    for (int idx = tid; idx < 288; idx += 256) sG[idx] = 0.f;
    __syncthreads();
#pragma unroll
    for (int i = 0; i < 4; i++)
#pragma unroll
        for (int j = 0; j < 4; j++)
            atomicAdd(&sG[(dg * 4 + i) * 16 + eg * 4 + j], acc[i][j]);
    if (eg == 0) {
#pragma unroll
        for (int i = 0; i < 4; i++) atomicAdd(&sG[256 + dg * 4 + i], aq[i]);
    }
    if (dg == 0) {
#pragma unroll
        for (int j = 0; j < 4; j++) atomicAdd(&sG[272 + eg * 4 + j], ak[j]);
    }
    __syncthreads();
    float* gg = g_gram + bh * 288;
    for (int idx = tid; idx < 288; idx += 256) atomicAdd(gg + idx, sG[idx]);
}

// ---------------- attn: normalize gram, softmax, fold with proj into A (bf16 split) --
__global__ __launch_bounds__(256) void attn_k(
    const float* __restrict__ temp, const float* __restrict__ proj_w)
{
    const int b = blockIdx.x;
    const int part = blockIdx.y;
    const int tid = threadIdx.x;
    const long aBase = (long)b * 128 * 256;

    if (part == 8) {
        for (int idx = tid; idx < 128 * 128; idx += 256) {
            int c = idx >> 7, j = idx & 127;
            __nv_bfloat16 h, l;
            split2(proj_w[c * 256 + 128 + j], h, l);
            g_Ah[aBase + c * 256 + 128 + j] = h;
            g_Al[aBase + c * 256 + 128 + j] = l;
        }
        return;
    }
    const int h = part;
    const float* gg = g_gram + (b * 8 + h) * 288;
    __shared__ float sA[256], sqn[16], skn[16], srm[16], srs[16];
    if (tid < 16) {
        sqn[tid] = fmaxf(sqrtf(gg[256 + tid]), 1e-12f);
        skn[tid] = fmaxf(sqrtf(gg[272 + tid]), 1e-12f);
    }
    __syncthreads();
    const int d = tid >> 4, e = tid & 15;
    float val = gg[d * 16 + e] / (sqn[d] * skn[e]) * temp[h];
    sA[tid] = val;
    __syncthreads();
    if (e == 0) {
        float m = -1e30f;
        for (int j = 0; j < 16; j++) m = fmaxf(m, sA[d * 16 + j]);
        srm[d] = m;
    }
    __syncthreads();
    float p = expf(val - srm[d]);
    sA[tid] = p;
    __syncthreads();
    if (e == 0) {
        float ssum = 0.f;
        for (int j = 0; j < 16; j++) ssum += sA[d * 16 + j];
        srs[d] = ssum;
    }
    __syncthreads();
    sA[tid] = p / srs[d];
    __syncthreads();
    for (int o = tid; o < 2048; o += 256) {
        int c = o >> 4, ee = o & 15;
        float accv = 0.f;
#pragma unroll
        for (int dd = 0; dd < 16; dd++)
            accv += proj_w[c * 256 + h * 16 + dd] * sA[dd * 16 + ee];
        __nv_bfloat16 hh, ll;
        split2(accv, hh, ll);
        g_Ah[aBase + c * 256 + h * 16 + ee] = hh;
        g_Al[aBase + c * 256 + h * 16 + ee] = ll;
    }
}

// ---------------- launch ----------------
extern "C" void kernel_launch(void* const* d_in, const int* in_sizes, int n_in,
                              void* d_out, int out_size)
{
    const float* x      = (const float*)d_in[0];
    const float* pos_w  = (const float*)d_in[1];
    const float* pos_b  = (const float*)d_in[2];
    const float* qd3_w  = (const float*)d_in[3];
    const float* qd3_b  = (const float*)d_in[4];
    const float* qd5_w  = (const float*)d_in[5];
    const float* qd5_b  = (const float*)d_in[6];
    const float* temp   = (const float*)d_in[7];
    const float* d3_w   = (const float*)d_in[8];
    const float* d3_b   = (const float*)d_in[9];
    const float* d5_w   = (const float*)d_in[10];
    const float* d5_b   = (const float*)d_in[11];
    const float* proj_w = (const float*)d_in[12];
    float* out = (float*)d_out;

    zero_gram_k<<<72, 256>>>();
    convert_w_k<<<48, 256>>>(pos_w);
    k1_gemm<<<dim3(128, 6, 8), 128>>>(x, pos_b);
    dualconv_k<0><<<dim3(8, 192, 8), 128>>>(nullptr, qd3_w, qd3_b, qd5_w, qd5_b);
    dualconv_k<1><<<dim3(8, 64, 8), 128>>>(x, d3_w, d3_b, d5_w, d5_b);
    gram_k<<<dim3(64, 16), 256>>>();
    attn_k<<<dim3(8, 9), 256>>>(temp, proj_w);
    k4_gemm<<<dim3(128, 2, 8), 128>>>(out);
}